// round 9
// baseline (speedup 1.0000x reference)
#include <cuda_runtime.h>
#include <cuda_bf16.h>

#define C1SSIM 1.0e-4f
#define C2SSIM 9.0e-4f

// Gaussian window (WIN=11, sigma=1.5), precomputed; becomes FFMA immediates.
#define GW_INIT {0.00102838f, 0.00759876f, 0.03600076f, 0.10936076f, 0.21300551f, \
                 0.26601166f, 0.21300551f, 0.10936076f, 0.03600076f, 0.00759876f, 0.00102838f}

// scratch (allocation-free: __device__ globals). +16 pad: conv window over-read.
__device__ __align__(16) float d_qn[15 * 64 * 441 + 16];  // normalized queries [b][c][p]
__device__ __align__(16) float d_sn[25 * 64 * 441 + 16];  // normalized supports [ns][c][p]
__device__ float d_mu[40 * 64 * 121];                      // gaussian mean per image-channel
__device__ float d_sg[40 * 64 * 121];                      // variance E[x^2]-mu^2
__device__ __align__(16) float d_part[75 * 64];            // per (b,n,c) ssim-sum
__device__ int d_count;                                    // completion counter (self-resetting)

// KA: fused normalize+transpose+stats. One block per image (40 blocks, 256 threads).
__global__ void k_prep(const float* __restrict__ x1, const float* __restrict__ x2) {
    const float GW[11] = GW_INIT;
    __shared__ float t[64][65];     // transpose tile (64 positions)
    __shared__ float xb[8][448];    // per-warp channel row
    __shared__ float hb1[8][232];   // per-warp h-conv scratch
    __shared__ float hb2[8][232];
    int img = blockIdx.x;           // 0..39
    int tid = threadIdx.x, w = tid >> 5, lane = tid & 31;
    const float* src = (img < 15) ? (x1 + img * 441 * 64) : (x2 + (img - 15) * 441 * 64);
    float* dst = (img < 15) ? (d_qn + img * 64 * 441) : (d_sn + (img - 15) * 64 * 441);

    // ---- phase 1: normalize per position, transpose (p,c)->(c,p), write global ----
    int pl = tid >> 2, cg = tid & 3;   // position-local (0..63), channel-group (0..3)
    for (int it = 0; it < 7; it++) {
        int p0 = it * 64;
        int p = p0 + pl;
        float4 v[4];
        float ss = 0.f;
        if (p < 441) {
            const float4* s4 = (const float4*)(src + p * 64 + cg * 16);
#pragma unroll
            for (int i = 0; i < 4; i++) {
                v[i] = s4[i];
                ss += v[i].x * v[i].x + v[i].y * v[i].y + v[i].z * v[i].z + v[i].w * v[i].w;
            }
        }
        ss += __shfl_xor_sync(0xffffffffu, ss, 1);
        ss += __shfl_xor_sync(0xffffffffu, ss, 2);
        float inv = rsqrtf(ss);
        if (p < 441) {
#pragma unroll
            for (int i = 0; i < 4; i++) {
                int c = cg * 16 + 4 * i;
                t[c + 0][pl] = v[i].x * inv;
                t[c + 1][pl] = v[i].y * inv;
                t[c + 2][pl] = v[i].z * inv;
                t[c + 3][pl] = v[i].w * inv;
            }
        }
        __syncthreads();
        int np = min(64, 441 - p0);
        for (int i = tid; i < 64 * 64; i += 256) {
            int c = i >> 6, pp = i & 63;
            if (pp < np) dst[c * 441 + p0 + pp] = t[c][pp];   // coalesced across pp
        }
        __syncthreads();   // t reused next iter
    }
    // global writes above are visible block-wide after the last __syncthreads

    // ---- phase 2: warp-per-channel stats (8 warps x 8 channels) ----
    float* xw = xb[w]; float* h1w = hb1[w]; float* h2w = hb2[w];
    for (int ci = 0; ci < 8; ci++) {
        int c = w * 8 + ci;
        const float* row = dst + c * 441;
        for (int i = lane; i < 441; i += 32) xw[i] = row[i];
        __syncwarp();
        for (int o = lane; o < 231; o += 32) {   // 21 rows x 11 cols
            int r = o / 11, j = o - 11 * r;
            const float* xr = xw + r * 21 + j;
            float s1 = 0.f, s2 = 0.f;
#pragma unroll
            for (int k = 0; k < 11; k++) { float v = xr[k]; s1 = fmaf(GW[k], v, s1); s2 = fmaf(GW[k] * v, v, s2); }
            h1w[o] = s1; h2w[o] = s2;
        }
        __syncwarp();
        int id = img * 64 + c;
        for (int o = lane; o < 121; o += 32) {   // 11 x 11
            int i = o / 11, j = o - 11 * i;
            float m = 0.f, m2 = 0.f;
#pragma unroll
            for (int k = 0; k < 11; k++) {
                m  = fmaf(GW[k], h1w[(i + k) * 11 + j], m);
                m2 = fmaf(GW[k], h2w[(i + k) * 11 + j], m2);
            }
            d_mu[id * 121 + o] = m;
            d_sg[id * 121 + o] = m2 - m * m;
        }
        __syncwarp();   // scratch reused next channel
    }
}

// KB: block per (b,n,c); all shots staged; 2 main barriers; fused device-wide final
// reduce in the last-arriving block (self-resetting counter).
__global__ void k_cross6(float* __restrict__ out) {
    const float GW[11] = GW_INIT;
    int c = blockIdx.x, n = blockIdx.y, b = blockIdx.z;
    __shared__ float q[448];
    __shared__ float sm[5][444];
    __shared__ float h[5][232];
    __shared__ float red[4];
    __shared__ int is_last;
    int tid = threadIdx.x, w = tid >> 5, lane = tid & 31;

    // stage q and all 5 support rows (coalesced)
    const float* qrow = d_qn + (b * 64 + c) * 441;
    for (int i = tid; i < 441; i += 128) q[i] = qrow[i];
#pragma unroll
    for (int s = 0; s < 5; s++) {
        const float* sr = d_sn + ((n * 5 + s) * 64 + c) * 441;
        for (int i = tid; i < 441; i += 128) sm[s][i] = sr[i];
    }

    // prefetch per-pixel stats into registers (latency hides under barrier 1)
    float mu1 = 0.f, sg1 = 0.f, mu2r[5], sg2r[5];
    if (tid < 121) {
        mu1 = d_mu[(b * 64 + c) * 121 + tid];
        sg1 = d_sg[(b * 64 + c) * 121 + tid];
#pragma unroll
        for (int s = 0; s < 5; s++) {
            int sbase = ((15 + n * 5 + s) * 64 + c) * 121 + tid;
            mu2r[s] = d_mu[sbase];
            sg2r[s] = d_sg[sbase];
        }
    }
    float mu1sq = mu1 * mu1;
    __syncthreads();   // barrier 1: q, sm ready

    // phase A: horizontal conv of q*s for ALL shots
    int r1 = tid / 6, g1 = tid - r1 * 6;
    int j0 = g1 * 2, nout1 = (g1 == 5) ? 1 : 2;
    int base1 = r1 * 21 + j0;
    if (tid < 126) {
        float qw[12];
#pragma unroll
        for (int k = 0; k < 12; k++) qw[k] = q[base1 + k];
#pragma unroll
        for (int s = 0; s < 5; s++) {
            float z[12];
#pragma unroll
            for (int k = 0; k < 12; k++) z[k] = qw[k] * sm[s][base1 + k];
            float sv0 = 0.f, sv1 = 0.f;
#pragma unroll
            for (int k = 0; k < 11; k++) {
                sv0 = fmaf(GW[k], z[k], sv0);
                sv1 = fmaf(GW[k], z[k + 1], sv1);
            }
            h[s][r1 * 11 + j0] = sv0;
            if (nout1 == 2) h[s][r1 * 11 + j0 + 1] = sv1;
        }
    }
    __syncthreads();   // barrier 2: all h ready

    // phase B: vertical conv + SSIM; per-thread accumulator across shots
    float accv = 0.f;
    if (tid < 121) {
        int i2 = tid / 11, j2 = tid - i2 * 11;
#pragma unroll
        for (int s = 0; s < 5; s++) {
            const float* hb = h[s] + i2 * 11 + j2;
            float t12 = 0.f;
#pragma unroll
            for (int k = 0; k < 11; k++) t12 = fmaf(GW[k], hb[k * 11], t12);
            float mu2 = mu2r[s], sg2 = sg2r[s];
            float m12 = mu1 * mu2;
            float num = (2.f * m12 + C1SSIM) * (2.f * (t12 - m12) + C2SSIM);
            float den = (mu1sq + mu2 * mu2 + C1SSIM) * (sg1 + sg2 + C2SSIM);
            accv += num / den;
        }
    }
#pragma unroll
    for (int off = 16; off > 0; off >>= 1) accv += __shfl_down_sync(0xffffffffu, accv, off);
    if (lane == 0) red[w] = accv;
    __syncthreads();

    // fused final: last block sums channels and writes out
    if (tid == 0) {
        d_part[(b * 5 + n) * 64 + c] = red[0] + red[1] + red[2] + red[3];
        __threadfence();
        int old = atomicAdd(&d_count, 1);
        is_last = (old == 64 * 5 * 15 - 1) ? 1 : 0;
    }
    __syncthreads();
    if (is_last) {
        __threadfence();   // acquire: all blocks' d_part writes visible
        if (tid < 75) {
            const float4* p4 = (const float4*)(d_part + tid * 64);
            float ssum = 0.f;
#pragma unroll
            for (int k = 0; k < 16; k++) { float4 tv = p4[k]; ssum += tv.x + tv.y + tv.z + tv.w; }
            out[tid] = ssum * (1.0f / (64.0f * 121.0f));
        }
        if (tid == 0) d_count = 0;   // self-reset for graph replay
    }
}

extern "C" void kernel_launch(void* const* d_in, const int* in_sizes, int n_in,
                              void* d_out, int out_size) {
    const float* x1 = (const float*)d_in[0];   // (15, 441, 64)
    const float* x2 = (const float*)d_in[1];   // (5, 5, 441, 64)
    float* out = (float*)d_out;                // (15, 5)

    k_prep<<<40, 256>>>(x1, x2);
    dim3 g3(64, 5, 15);
    k_cross6<<<g3, 128>>>(out);
}

// round 10
// speedup vs baseline: 1.8713x; 1.8713x over previous
#include <cuda_runtime.h>
#include <cuda_bf16.h>

#define C1SSIM 1.0e-4f
#define C2SSIM 9.0e-4f

// Gaussian window (WIN=11, sigma=1.5), precomputed; becomes FFMA immediates.
#define GW_INIT {0.00102838f, 0.00759876f, 0.03600076f, 0.10936076f, 0.21300551f, \
                 0.26601166f, 0.21300551f, 0.10936076f, 0.03600076f, 0.00759876f, 0.00102838f}

// Padded image-channel rows: 21 rows x 24 floats (21 data + 3 pad) = 504 floats.
// Zero-initialized device globals -> padding reads are benign zeros.
__device__ __align__(16) float d_qn[15 * 64 * 504];  // normalized queries [b][c][r*24+col]
__device__ __align__(16) float d_sn[25 * 64 * 504];  // normalized supports [ns][c][r*24+col]
__device__ float d_mu[40 * 64 * 121];                 // gaussian mean per image-channel
__device__ float d_sg[40 * 64 * 121];                 // variance E[x^2]-mu^2
__device__ __align__(16) float d_part[75 * 64];       // per (b,n,c) ssim-sum

// K1: per-position channel L2-normalize + transpose (p,c)->(c, r*24+col), padded layout.
__global__ void k_norm3(const float* __restrict__ x1, const float* __restrict__ x2) {
    int img = blockIdx.x;                    // 0..39
    int p0 = blockIdx.y * 64;
    int tid = threadIdx.x;
    int pl = tid >> 2, cg = tid & 3;         // position-local, channel-group
    int p = p0 + pl;
    const float* src = (img < 15) ? (x1 + img * 441 * 64) : (x2 + (img - 15) * 441 * 64);
    float* dst = (img < 15) ? (d_qn + img * 64 * 504) : (d_sn + (img - 15) * 64 * 504);

    __shared__ float t[64][65];

    float4 v[4];
    float ss = 0.f;
    if (p < 441) {
        const float4* s4 = (const float4*)(src + p * 64 + cg * 16);
#pragma unroll
        for (int i = 0; i < 4; i++) {
            v[i] = s4[i];
            ss += v[i].x * v[i].x + v[i].y * v[i].y + v[i].z * v[i].z + v[i].w * v[i].w;
        }
    }
    ss += __shfl_xor_sync(0xffffffffu, ss, 1);
    ss += __shfl_xor_sync(0xffffffffu, ss, 2);
    float inv = rsqrtf(ss);
    if (p < 441) {
#pragma unroll
        for (int i = 0; i < 4; i++) {
            int c = cg * 16 + 4 * i;
            t[c + 0][pl] = v[i].x * inv;
            t[c + 1][pl] = v[i].y * inv;
            t[c + 2][pl] = v[i].z * inv;
            t[c + 3][pl] = v[i].w * inv;
        }
    }
    __syncthreads();
    for (int i = tid; i < 64 * 64; i += 256) {
        int c = i >> 6, pp = i & 63;
        int pg = p0 + pp;
        if (pg < 441) {
            int r = pg / 21, col = pg - 21 * r;
            dst[c * 504 + r * 24 + col] = t[c][pp];
        }
    }
}

// K2: warp-per-channel stats from padded layout: mu, sigma^2 per image-channel.
__global__ void k_stats2() {
    const float GW[11] = GW_INIT;
    __shared__ float x[4][448];
    __shared__ float h1[4][232];
    __shared__ float h2[4][232];
    int tid = threadIdx.x, w = tid >> 5, lane = tid & 31;
    int id = blockIdx.x * 4 + w;     // img*64 + c
    int img = id >> 6, c = id & 63;
    const float* row = (img < 15) ? (d_qn + (img * 64 + c) * 504)
                                  : (d_sn + ((img - 15) * 64 + c) * 504);
    float* xw = x[w]; float* h1w = h1[w]; float* h2w = h2[w];

    for (int i = lane; i < 504; i += 32) {      // coalesced; drop pad cols
        int r = i / 24, col = i - 24 * r;
        if (col < 21) xw[r * 21 + col] = row[i];
    }
    __syncwarp();
    for (int o = lane; o < 231; o += 32) {   // 21 rows x 11 cols
        int r = o / 11, j = o - 11 * r;
        const float* xr = xw + r * 21 + j;
        float s1 = 0.f, s2 = 0.f;
#pragma unroll
        for (int k = 0; k < 11; k++) { float v = xr[k]; s1 = fmaf(GW[k], v, s1); s2 = fmaf(GW[k] * v, v, s2); }
        h1w[o] = s1; h2w[o] = s2;
    }
    __syncwarp();
    for (int o = lane; o < 121; o += 32) {   // 11 x 11
        int i = o / 11, j = o - 11 * i;
        float m = 0.f, m2 = 0.f;
#pragma unroll
        for (int k = 0; k < 11; k++) {
            m  = fmaf(GW[k], h1w[(i + k) * 11 + j], m);
            m2 = fmaf(GW[k], h2w[(i + k) * 11 + j], m2);
        }
        d_mu[id * 121 + o] = m;
        d_sg[id * 121 + o] = m2 - m * m;
    }
}

// K3: block per (b,n,c); serial shots; vectorized conv:
//  phase A: 63 threads x 4 outputs, LDG.128 from padded global, STS.128 to h (stride 12)
//  phase B: 121 threads x 1 output, registers-resident stats. Tiny smem (~1KB).
__global__ void k_cross7() {
    const float GW[11] = GW_INIT;
    int c = blockIdx.x, n = blockIdx.y, b = blockIdx.z;
    __shared__ __align__(16) float h[21 * 12];   // 252: h-conv out, row stride 12 (11 data + 1 pad)
    __shared__ float red[4];
    int tid = threadIdx.x, w = tid >> 5, lane = tid & 31;

    // stats prefetch (latency hides under phase A of shot 0)
    float mu1 = 0.f, sg1 = 0.f, mu2r[5], sg2r[5];
    if (tid < 121) {
        mu1 = d_mu[(b * 64 + c) * 121 + tid];
        sg1 = d_sg[(b * 64 + c) * 121 + tid];
#pragma unroll
        for (int s = 0; s < 5; s++) {
            int sbase = ((15 + n * 5 + s) * 64 + c) * 121 + tid;
            mu2r[s] = d_mu[sbase];
            sg2r[s] = d_sg[sbase];
        }
    }
    float mu1sq = mu1 * mu1;

    // phase A map: tid<63 -> row r1 (0..20), group g1 (0..2), outputs j = 4*g1 .. (+3)
    int r1 = tid / 3, g1 = tid - 3 * r1;
    int aoff = r1 * 24 + 4 * g1;           // window start within padded row-image
    float qw[16];
    if (tid < 63) {
        const float4* qp = (const float4*)(d_qn + (b * 64 + c) * 504 + aoff);
#pragma unroll
        for (int i = 0; i < 4; i++) *(float4*)&qw[4 * i] = qp[i];
    }
    int i2 = tid / 11, j2 = tid - 11 * i2;  // phase B map (tid<121)

    float accv = 0.f;
#pragma unroll
    for (int s = 0; s < 5; s++) {
        // ---- phase A: horizontal conv of q*s, 4 outputs/thread ----
        if (tid < 63) {
            const float4* sp = (const float4*)(d_sn + ((n * 5 + s) * 64 + c) * 504 + aoff);
            float z[16];
#pragma unroll
            for (int i = 0; i < 4; i++) {
                float4 sv = sp[i];
                z[4 * i + 0] = qw[4 * i + 0] * sv.x;
                z[4 * i + 1] = qw[4 * i + 1] * sv.y;
                z[4 * i + 2] = qw[4 * i + 2] * sv.z;
                z[4 * i + 3] = qw[4 * i + 3] * sv.w;
            }
            float o0 = 0.f, o1 = 0.f, o2 = 0.f, o3 = 0.f;
#pragma unroll
            for (int k = 0; k < 11; k++) {
                o0 = fmaf(GW[k], z[k + 0], o0);
                o1 = fmaf(GW[k], z[k + 1], o1);
                o2 = fmaf(GW[k], z[k + 2], o2);
                o3 = fmaf(GW[k], z[k + 3], o3);   // g1==2,m==3 -> pad slot, never read
            }
            *(float4*)&h[r1 * 12 + 4 * g1] = make_float4(o0, o1, o2, o3);
        }
        __syncthreads();   // h ready

        // ---- phase B: vertical conv + SSIM accumulate ----
        if (tid < 121) {
            const float* hb = h + i2 * 12 + j2;
            float t12 = 0.f;
#pragma unroll
            for (int k = 0; k < 11; k++) t12 = fmaf(GW[k], hb[k * 12], t12);
            float mu2 = mu2r[s], sg2 = sg2r[s];
            float m12 = mu1 * mu2;
            float num = (2.f * m12 + C1SSIM) * (2.f * (t12 - m12) + C2SSIM);
            float den = (mu1sq + mu2 * mu2 + C1SSIM) * (sg1 + sg2 + C2SSIM);
            accv += num / den;
        }
        __syncthreads();   // h consumed before next shot overwrites
    }

    // single deterministic block reduction
#pragma unroll
    for (int off = 16; off > 0; off >>= 1) accv += __shfl_down_sync(0xffffffffu, accv, off);
    if (lane == 0) red[w] = accv;
    __syncthreads();
    if (tid == 0) d_part[(b * 5 + n) * 64 + c] = red[0] + red[1] + red[2] + red[3];
}

// K4: reduce channels, scale by 1/(C*H'*W')
__global__ void k_final(float* __restrict__ out) {
    int o = blockIdx.x;  // 0..74 == b*5 + n
    const float4* p4 = (const float4*)(d_part + o * 64);
    float4 t = p4[threadIdx.x & 15];
    float v = t.x + t.y + t.z + t.w;   // 16 lanes cover 64 values
    v = (threadIdx.x < 16) ? v : 0.f;
#pragma unroll
    for (int off = 8; off > 0; off >>= 1) v += __shfl_down_sync(0xffffffffu, v, off);
    if (threadIdx.x == 0) out[o] = v * (1.0f / (64.0f * 121.0f));
}

extern "C" void kernel_launch(void* const* d_in, const int* in_sizes, int n_in,
                              void* d_out, int out_size) {
    const float* x1 = (const float*)d_in[0];   // (15, 441, 64)
    const float* x2 = (const float*)d_in[1];   // (5, 5, 441, 64)
    float* out = (float*)d_out;                // (15, 5)

    dim3 g1(40, 7);
    k_norm3<<<g1, 256>>>(x1, x2);
    k_stats2<<<640, 128>>>();
    dim3 g3(64, 5, 15);
    k_cross7<<<g3, 128>>>();
    k_final<<<75, 32>>>(out);
}